// round 5
// baseline (speedup 1.0000x reference)
#include <cuda_runtime.h>
#include <cstring>

// Fused JPEG round-trip. Thread owns TWO horizontally adjacent 8x8 blocks,
// all three channels packed f32x2 {block0,block1}. Transposes via per-warp
// bank-conflict-free smem. Inverse color + normalize folded to one affine.
// Input : d_in[0] = float32 [1,3,2048,2048]; Output: float32 [1,3*2048*2048]

#define IMG_W  2048
#define IMG_H  2048
#define PLANE  (IMG_W * IMG_H)

// DCT basis constants (fp32 round of the reference matrix entries)
#define C1 0.4903926402f
#define C2 0.4619397663f
#define C3 0.4157348062f
#define C4 0.3535533906f
#define C5 0.2777851165f
#define C6 0.1913417162f
#define C7 0.0975451610f

// Quant tables, luma then chroma (Q=50 -> s=1)
__constant__ float cQf[128] = {
    16,11,10,16,24,40,51,61,  12,12,14,19,26,58,60,55,
    14,13,16,24,40,57,69,56,  14,17,22,29,51,87,80,62,
    18,22,37,56,68,109,103,77, 24,35,55,64,81,104,113,92,
    49,64,78,87,103,121,120,101, 72,92,95,98,112,100,103,99,
    17,18,24,47,99,99,99,99,  18,21,26,66,99,99,99,99,
    24,26,56,99,99,99,99,99,  47,66,99,99,99,99,99,99,
    99,99,99,99,99,99,99,99,  99,99,99,99,99,99,99,99,
    99,99,99,99,99,99,99,99,  99,99,99,99,99,99,99,99 };
__constant__ float cRQf[128] = {
    1.f/16,1.f/11,1.f/10,1.f/16,1.f/24,1.f/40,1.f/51,1.f/61,
    1.f/12,1.f/12,1.f/14,1.f/19,1.f/26,1.f/58,1.f/60,1.f/55,
    1.f/14,1.f/13,1.f/16,1.f/24,1.f/40,1.f/57,1.f/69,1.f/56,
    1.f/14,1.f/17,1.f/22,1.f/29,1.f/51,1.f/87,1.f/80,1.f/62,
    1.f/18,1.f/22,1.f/37,1.f/56,1.f/68,1.f/109,1.f/103,1.f/77,
    1.f/24,1.f/35,1.f/55,1.f/64,1.f/81,1.f/104,1.f/113,1.f/92,
    1.f/49,1.f/64,1.f/78,1.f/87,1.f/103,1.f/121,1.f/120,1.f/101,
    1.f/72,1.f/92,1.f/95,1.f/98,1.f/112,1.f/100,1.f/103,1.f/99,
    1.f/17,1.f/18,1.f/24,1.f/47,1.f/99,1.f/99,1.f/99,1.f/99,
    1.f/18,1.f/21,1.f/26,1.f/66,1.f/99,1.f/99,1.f/99,1.f/99,
    1.f/24,1.f/26,1.f/56,1.f/99,1.f/99,1.f/99,1.f/99,1.f/99,
    1.f/47,1.f/66,1.f/99,1.f/99,1.f/99,1.f/99,1.f/99,1.f/99,
    1.f/99,1.f/99,1.f/99,1.f/99,1.f/99,1.f/99,1.f/99,1.f/99,
    1.f/99,1.f/99,1.f/99,1.f/99,1.f/99,1.f/99,1.f/99,1.f/99,
    1.f/99,1.f/99,1.f/99,1.f/99,1.f/99,1.f/99,1.f/99,1.f/99,
    1.f/99,1.f/99,1.f/99,1.f/99,1.f/99,1.f/99,1.f/99,1.f/99 };

// Folded inverse-color + normalization: out_c = NC_Ac*y + NC_Bc*u + NC_Cc*v + NC_Kc
// (derived in double from inv(W), mean, std; out = (rgb - mean_px)/std_px)
#define NC_A0 0.0158730159f
#define NC_B0 (-1.93476190e-8f)
#define NC_C0 0.0222539619f
#define NC_K0 (-4.8373935f)
#define NC_A1 0.0161030596f
#define NC_B1 (-0.0055416377f)
#define NC_C1 (-0.0114997768f)
#define NC_K1 0.2006247f
#define NC_A2 0.0149925037f
#define NC_B2 0.0265667181f
#define NC_C2 6.09145427e-9f
#define NC_K2 (-5.1081869f)

typedef unsigned long long ull;

// ---- packed f32x2 helpers ----
__device__ __forceinline__ ull pk(float lo, float hi) {
    float2 t = make_float2(lo, hi); ull r; memcpy(&r, &t, 8); return r;
}
__device__ __forceinline__ ull pk1(float x) { return pk(x, x); }
__device__ __forceinline__ float2 unpk(ull a) {
    float2 t; memcpy(&t, &a, 8); return t;
}
__device__ __forceinline__ ull padd(ull a, ull b) {
    ull r; asm("add.rn.f32x2 %0,%1,%2;" : "=l"(r) : "l"(a), "l"(b)); return r;
}
__device__ __forceinline__ ull pmul(ull a, ull b) {
    ull r; asm("mul.rn.f32x2 %0,%1,%2;" : "=l"(r) : "l"(a), "l"(b)); return r;
}
__device__ __forceinline__ ull pfma(ull a, ull b, ull c) {
    ull r; asm("fma.rn.f32x2 %0,%1,%2,%3;" : "=l"(r) : "l"(a), "l"(b), "l"(c)); return r;
}
__device__ __forceinline__ ull psub(ull a, ull b) { return pfma(b, pk1(-1.0f), a); } // exact a-b

// ---- packed 8-pt transforms (bit-identical per half to the scalar versions) ----
__device__ __forceinline__ void fdct8p(ull v[8]) {
    ull e0=padd(v[0],v[7]), e1=padd(v[1],v[6]), e2=padd(v[2],v[5]), e3=padd(v[3],v[4]);
    ull o0=psub(v[0],v[7]), o1=psub(v[1],v[6]), o2=psub(v[2],v[5]), o3=psub(v[3],v[4]);
    ull s03=padd(e0,e3), s12=padd(e1,e2), d03=psub(e0,e3), d12=psub(e1,e2);
    v[0]=pmul(pk1(C4), padd(s03,s12));
    v[4]=pmul(pk1(C4), psub(s03,s12));
    v[2]=pfma(pk1(C2),d03, pmul(pk1( C6),d12));
    v[6]=pfma(pk1(C6),d03, pmul(pk1(-C2),d12));
    v[1]=pfma(pk1(C1),o0, pfma(pk1( C3),o1, pfma(pk1( C5),o2, pmul(pk1( C7),o3))));
    v[3]=pfma(pk1(C3),o0, pfma(pk1(-C7),o1, pfma(pk1(-C1),o2, pmul(pk1(-C5),o3))));
    v[5]=pfma(pk1(C5),o0, pfma(pk1(-C1),o1, pfma(pk1( C7),o2, pmul(pk1( C3),o3))));
    v[7]=pfma(pk1(C7),o0, pfma(pk1(-C5),o1, pfma(pk1( C3),o2, pmul(pk1(-C1),o3))));
}
__device__ __forceinline__ void idct8p(ull v[8]) {
    ull sp=pmul(pk1(C4), padd(v[0],v[4]));
    ull sm=pmul(pk1(C4), psub(v[0],v[4]));
    ull t1=pfma(pk1(C2),v[2], pmul(pk1( C6),v[6]));
    ull t2=pfma(pk1(C6),v[2], pmul(pk1(-C2),v[6]));
    ull E0=padd(sp,t1), E1=padd(sm,t2), E2=psub(sm,t2), E3=psub(sp,t1);
    ull O0=pfma(pk1(C1),v[1], pfma(pk1( C3),v[3], pfma(pk1( C5),v[5], pmul(pk1( C7),v[7]))));
    ull O1=pfma(pk1(C3),v[1], pfma(pk1(-C7),v[3], pfma(pk1(-C1),v[5], pmul(pk1(-C5),v[7]))));
    ull O2=pfma(pk1(C5),v[1], pfma(pk1(-C1),v[3], pfma(pk1( C7),v[5], pmul(pk1( C3),v[7]))));
    ull O3=pfma(pk1(C7),v[1], pfma(pk1(-C5),v[3], pfma(pk1( C3),v[5], pmul(pk1(-C1),v[7]))));
    v[0]=padd(E0,O0); v[7]=psub(E0,O0);
    v[1]=padd(E1,O1); v[6]=psub(E1,O1);
    v[2]=padd(E2,O2); v[5]=psub(E2,O2);
    v[3]=padd(E3,O3); v[4]=psub(E3,O3);
}

// ---- smem transpose across 8 lanes of a group (bank-conflict-free) ----
// lane r wrote v[k] at wrow[k] (= group_base + 10*r + k);
// lane r reads v[k] from group_base[10*k + r].
__device__ __forceinline__ void xposeS(ull v[8], ull* wrow, const ull* gbase, int r)
{
    #pragma unroll
    for (int k = 0; k < 8; k += 2)
        *reinterpret_cast<ulonglong2*>(wrow + k) = make_ulonglong2(v[k], v[k+1]);
    __syncwarp();
    #pragma unroll
    for (int k = 0; k < 8; ++k) v[k] = gbase[10 * k + r];
    __syncwarp();
}

// ---- quant/dequant of one packed coefficient pair ----
__device__ __forceinline__ ull quant_pair(ull sv, float q, float rq, float nq)
{
    float2 s = unpk(sv);
    float d0 = s.x * rq,  d1 = s.y * rq;
    float r0 = rintf(d0), r1 = rintf(d1);
    float e0 = fmaf(r0, nq, s.x) * rq;
    float e1 = fmaf(r1, nq, s.y) * rq;
    float o0 = fmaf(e0 * e0, e0, r0) * q;
    float o1 = fmaf(e1 * e1, e1, r1) * q;
    return pk(o0, o1);
}

__global__ __launch_bounds__(256, 2)
void jpeg_roundtrip_kernel(const float* __restrict__ in, float* __restrict__ out)
{
    // per-warp transpose scratch: 8 warps x 336 ull (group pitch 84, row pitch 10)
    __shared__ __align__(16) ull xb[8 * 336];
    // interleaved (q, rq) tables: [ch][i][r][2]
    __shared__ float qt[256];

    const int tid  = threadIdx.x;
    const int warp = tid >> 5;
    const int lane = tid & 31;
    const int r    = lane >> 2;
    const int g    = lane & 3;

    {   // build interleaved quant table
        int w  = tid & 1, rr = (tid >> 1) & 7, ii = (tid >> 4) & 7, ch = tid >> 7;
        int si = ch * 64 + ii * 8 + rr;
        qt[tid] = w ? cRQf[si] : cQf[si];
    }

    ull* gbase = xb + warp * 336 + g * 84;
    ull* wrow  = gbase + 10 * r;

    const int p   = warp * 4 + g;                  // block-pair index in CTA
    const int x0  = blockIdx.x * 512 + p * 16;
    const int y   = blockIdx.y * 8 + r;
    const int base = y * IMG_W + x0;

    // ---- load RGB (two blocks) ----
    float4 R0a = *(const float4*)(in + base);
    float4 R0b = *(const float4*)(in + base + 4);
    float4 R1a = *(const float4*)(in + base + 8);
    float4 R1b = *(const float4*)(in + base + 12);
    float4 G0a = *(const float4*)(in + base + PLANE);
    float4 G0b = *(const float4*)(in + base + PLANE + 4);
    float4 G1a = *(const float4*)(in + base + PLANE + 8);
    float4 G1b = *(const float4*)(in + base + PLANE + 12);
    float4 B0a = *(const float4*)(in + base + 2*PLANE);
    float4 B0b = *(const float4*)(in + base + 2*PLANE + 4);
    float4 B1a = *(const float4*)(in + base + 2*PLANE + 8);
    float4 B1b = *(const float4*)(in + base + 2*PLANE + 12);

    __syncthreads();   // quant table ready

    float Rc0[8] = {R0a.x,R0a.y,R0a.z,R0a.w, R0b.x,R0b.y,R0b.z,R0b.w};
    float Rc1[8] = {R1a.x,R1a.y,R1a.z,R1a.w, R1b.x,R1b.y,R1b.z,R1b.w};
    float Gc0[8] = {G0a.x,G0a.y,G0a.z,G0a.w, G0b.x,G0b.y,G0b.z,G0b.w};
    float Gc1[8] = {G1a.x,G1a.y,G1a.z,G1a.w, G1b.x,G1b.y,G1b.z,G1b.w};
    float Bc0[8] = {B0a.x,B0a.y,B0a.z,B0a.w, B0b.x,B0b.y,B0b.z,B0b.w};
    float Bc1[8] = {B1a.x,B1a.y,B1a.z,B1a.w, B1b.x,B1b.y,B1b.z,B1b.w};

    // ---- forward color, packed {block0, block1} ----
    ull Yp[8], Up[8], Vp[8];
    #pragma unroll
    for (int k = 0; k < 8; ++k) {
        ull Rp = pk(Rc0[k], Rc1[k]);
        ull Gp = pk(Gc0[k], Gc1[k]);
        ull Bp = pk(Bc0[k], Bc1[k]);
        Yp[k] = pfma(Bp, pk1(0.114f), pfma(Gp, pk1(0.587f), pmul(Rp, pk1(0.299f))));
        Up[k] = pfma(Rp, pk1(-0.168736f), pfma(Gp, pk1(-0.331264f), pfma(Bp, pk1(0.5f), pk1(128.0f))));
        Vp[k] = pfma(Rp, pk1(0.5f), pfma(Gp, pk1(-0.418688f), pfma(Bp, pk1(-0.081312f), pk1(128.0f))));
    }

    // ---- luma pipeline ----
    fdct8p(Yp); xposeS(Yp, wrow, gbase, r); fdct8p(Yp);
    #pragma unroll
    for (int i = 0; i < 8; ++i) {
        float2 qq = *(const float2*)(qt + i * 16 + r * 2);
        Yp[i] = quant_pair(Yp[i], qq.x, qq.y, -qq.x);
    }
    idct8p(Yp); xposeS(Yp, wrow, gbase, r); idct8p(Yp);

    // ---- U pipeline ----
    fdct8p(Up); xposeS(Up, wrow, gbase, r); fdct8p(Up);
    #pragma unroll
    for (int i = 0; i < 8; ++i) {
        float2 qq = *(const float2*)(qt + 128 + i * 16 + r * 2);
        Up[i] = quant_pair(Up[i], qq.x, qq.y, -qq.x);
    }
    idct8p(Up); xposeS(Up, wrow, gbase, r); idct8p(Up);

    // ---- V pipeline ----
    fdct8p(Vp); xposeS(Vp, wrow, gbase, r); fdct8p(Vp);
    #pragma unroll
    for (int i = 0; i < 8; ++i) {
        float2 qq = *(const float2*)(qt + 128 + i * 16 + r * 2);
        Vp[i] = quant_pair(Vp[i], qq.x, qq.y, -qq.x);
    }
    idct8p(Vp); xposeS(Vp, wrow, gbase, r); idct8p(Vp);

    // ---- folded inverse color + normalize, packed ----
    float Ro[8], R1o[8], Go[8], G1o[8], Bo[8], B1o[8];
    #pragma unroll
    for (int k = 0; k < 8; ++k) {
        ull Rp = pfma(Yp[k], pk1(NC_A0), pfma(Up[k], pk1(NC_B0), pfma(Vp[k], pk1(NC_C0), pk1(NC_K0))));
        ull Gp = pfma(Yp[k], pk1(NC_A1), pfma(Up[k], pk1(NC_B1), pfma(Vp[k], pk1(NC_C1), pk1(NC_K1))));
        ull Bp = pfma(Yp[k], pk1(NC_A2), pfma(Up[k], pk1(NC_B2), pfma(Vp[k], pk1(NC_C2), pk1(NC_K2))));
        float2 rv = unpk(Rp), gv = unpk(Gp), bv = unpk(Bp);
        Ro[k] = rv.x; R1o[k] = rv.y;
        Go[k] = gv.x; G1o[k] = gv.y;
        Bo[k] = bv.x; B1o[k] = bv.y;
    }
    *(float4*)(out + base)                 = make_float4(Ro[0],Ro[1],Ro[2],Ro[3]);
    *(float4*)(out + base + 4)             = make_float4(Ro[4],Ro[5],Ro[6],Ro[7]);
    *(float4*)(out + base + 8)             = make_float4(R1o[0],R1o[1],R1o[2],R1o[3]);
    *(float4*)(out + base + 12)            = make_float4(R1o[4],R1o[5],R1o[6],R1o[7]);
    *(float4*)(out + base + PLANE)         = make_float4(Go[0],Go[1],Go[2],Go[3]);
    *(float4*)(out + base + PLANE + 4)     = make_float4(Go[4],Go[5],Go[6],Go[7]);
    *(float4*)(out + base + PLANE + 8)     = make_float4(G1o[0],G1o[1],G1o[2],G1o[3]);
    *(float4*)(out + base + PLANE + 12)    = make_float4(G1o[4],G1o[5],G1o[6],G1o[7]);
    *(float4*)(out + base + 2*PLANE)       = make_float4(Bo[0],Bo[1],Bo[2],Bo[3]);
    *(float4*)(out + base + 2*PLANE + 4)   = make_float4(Bo[4],Bo[5],Bo[6],Bo[7]);
    *(float4*)(out + base + 2*PLANE + 8)   = make_float4(B1o[0],B1o[1],B1o[2],B1o[3]);
    *(float4*)(out + base + 2*PLANE + 12)  = make_float4(B1o[4],B1o[5],B1o[6],B1o[7]);
}

extern "C" void kernel_launch(void* const* d_in, const int* in_sizes, int n_in,
                              void* d_out, int out_size)
{
    const float* in = (const float*)d_in[0];
    float* out = (float*)d_out;
    dim3 grid(IMG_W / 512, IMG_H / 8);
    jpeg_roundtrip_kernel<<<grid, 256>>>(in, out);
}

// round 6
// speedup vs baseline: 1.0010x; 1.0010x over previous
#include <cuda_runtime.h>
#include <cstring>

// Fused JPEG round-trip. Thread owns TWO horizontally adjacent 8x8 blocks,
// all three channels packed f32x2 {block0,block1}. Y/U/V pipelines interleaved
// for ILP; transposes via per-warp bank-conflict-free smem (Y+U merged).
// Input : d_in[0] = float32 [1,3,2048,2048]; Output: float32 [1,3*2048*2048]

#define IMG_W  2048
#define IMG_H  2048
#define PLANE  (IMG_W * IMG_H)

// DCT basis constants (fp32 round of the reference matrix entries)
#define C1 0.4903926402f
#define C2 0.4619397663f
#define C3 0.4157348062f
#define C4 0.3535533906f
#define C5 0.2777851165f
#define C6 0.1913417162f
#define C7 0.0975451610f

// Quant tables, luma then chroma (Q=50 -> s=1)
__constant__ float cQf[128] = {
    16,11,10,16,24,40,51,61,  12,12,14,19,26,58,60,55,
    14,13,16,24,40,57,69,56,  14,17,22,29,51,87,80,62,
    18,22,37,56,68,109,103,77, 24,35,55,64,81,104,113,92,
    49,64,78,87,103,121,120,101, 72,92,95,98,112,100,103,99,
    17,18,24,47,99,99,99,99,  18,21,26,66,99,99,99,99,
    24,26,56,99,99,99,99,99,  47,66,99,99,99,99,99,99,
    99,99,99,99,99,99,99,99,  99,99,99,99,99,99,99,99,
    99,99,99,99,99,99,99,99,  99,99,99,99,99,99,99,99 };
__constant__ float cRQf[128] = {
    1.f/16,1.f/11,1.f/10,1.f/16,1.f/24,1.f/40,1.f/51,1.f/61,
    1.f/12,1.f/12,1.f/14,1.f/19,1.f/26,1.f/58,1.f/60,1.f/55,
    1.f/14,1.f/13,1.f/16,1.f/24,1.f/40,1.f/57,1.f/69,1.f/56,
    1.f/14,1.f/17,1.f/22,1.f/29,1.f/51,1.f/87,1.f/80,1.f/62,
    1.f/18,1.f/22,1.f/37,1.f/56,1.f/68,1.f/109,1.f/103,1.f/77,
    1.f/24,1.f/35,1.f/55,1.f/64,1.f/81,1.f/104,1.f/113,1.f/92,
    1.f/49,1.f/64,1.f/78,1.f/87,1.f/103,1.f/121,1.f/120,1.f/101,
    1.f/72,1.f/92,1.f/95,1.f/98,1.f/112,1.f/100,1.f/103,1.f/99,
    1.f/17,1.f/18,1.f/24,1.f/47,1.f/99,1.f/99,1.f/99,1.f/99,
    1.f/18,1.f/21,1.f/26,1.f/66,1.f/99,1.f/99,1.f/99,1.f/99,
    1.f/24,1.f/26,1.f/56,1.f/99,1.f/99,1.f/99,1.f/99,1.f/99,
    1.f/47,1.f/66,1.f/99,1.f/99,1.f/99,1.f/99,1.f/99,1.f/99,
    1.f/99,1.f/99,1.f/99,1.f/99,1.f/99,1.f/99,1.f/99,1.f/99,
    1.f/99,1.f/99,1.f/99,1.f/99,1.f/99,1.f/99,1.f/99,1.f/99,
    1.f/99,1.f/99,1.f/99,1.f/99,1.f/99,1.f/99,1.f/99,1.f/99,
    1.f/99,1.f/99,1.f/99,1.f/99,1.f/99,1.f/99,1.f/99,1.f/99 };

// Folded inverse-color + normalization: out_c = NC_Ac*y + NC_Bc*u + NC_Cc*v + NC_Kc
#define NC_A0 0.0158730159f
#define NC_B0 (-1.93476190e-8f)
#define NC_C0 0.0222539619f
#define NC_K0 (-4.8373935f)
#define NC_A1 0.0161030596f
#define NC_B1 (-0.0055416377f)
#define NC_C1 (-0.0114997768f)
#define NC_K1 0.2006247f
#define NC_A2 0.0149925037f
#define NC_B2 0.0265667181f
#define NC_C2 6.09145427e-9f
#define NC_K2 (-5.1081869f)

typedef unsigned long long ull;

// ---- packed f32x2 helpers ----
__device__ __forceinline__ ull pk(float lo, float hi) {
    float2 t = make_float2(lo, hi); ull r; memcpy(&r, &t, 8); return r;
}
__device__ __forceinline__ ull pk1(float x) { return pk(x, x); }
__device__ __forceinline__ float2 unpk(ull a) {
    float2 t; memcpy(&t, &a, 8); return t;
}
__device__ __forceinline__ ull padd(ull a, ull b) {
    ull r; asm("add.rn.f32x2 %0,%1,%2;" : "=l"(r) : "l"(a), "l"(b)); return r;
}
__device__ __forceinline__ ull pmul(ull a, ull b) {
    ull r; asm("mul.rn.f32x2 %0,%1,%2;" : "=l"(r) : "l"(a), "l"(b)); return r;
}
__device__ __forceinline__ ull pfma(ull a, ull b, ull c) {
    ull r; asm("fma.rn.f32x2 %0,%1,%2,%3;" : "=l"(r) : "l"(a), "l"(b), "l"(c)); return r;
}
__device__ __forceinline__ ull psub(ull a, ull b) { return pfma(b, pk1(-1.0f), a); } // exact a-b

// ---- packed 8-pt transforms ----
__device__ __forceinline__ void fdct8p(ull v[8]) {
    ull e0=padd(v[0],v[7]), e1=padd(v[1],v[6]), e2=padd(v[2],v[5]), e3=padd(v[3],v[4]);
    ull o0=psub(v[0],v[7]), o1=psub(v[1],v[6]), o2=psub(v[2],v[5]), o3=psub(v[3],v[4]);
    ull s03=padd(e0,e3), s12=padd(e1,e2), d03=psub(e0,e3), d12=psub(e1,e2);
    v[0]=pmul(pk1(C4), padd(s03,s12));
    v[4]=pmul(pk1(C4), psub(s03,s12));
    v[2]=pfma(pk1(C2),d03, pmul(pk1( C6),d12));
    v[6]=pfma(pk1(C6),d03, pmul(pk1(-C2),d12));
    v[1]=pfma(pk1(C1),o0, pfma(pk1( C3),o1, pfma(pk1( C5),o2, pmul(pk1( C7),o3))));
    v[3]=pfma(pk1(C3),o0, pfma(pk1(-C7),o1, pfma(pk1(-C1),o2, pmul(pk1(-C5),o3))));
    v[5]=pfma(pk1(C5),o0, pfma(pk1(-C1),o1, pfma(pk1( C7),o2, pmul(pk1( C3),o3))));
    v[7]=pfma(pk1(C7),o0, pfma(pk1(-C5),o1, pfma(pk1( C3),o2, pmul(pk1(-C1),o3))));
}
__device__ __forceinline__ void idct8p(ull v[8]) {
    ull sp=pmul(pk1(C4), padd(v[0],v[4]));
    ull sm=pmul(pk1(C4), psub(v[0],v[4]));
    ull t1=pfma(pk1(C2),v[2], pmul(pk1( C6),v[6]));
    ull t2=pfma(pk1(C6),v[2], pmul(pk1(-C2),v[6]));
    ull E0=padd(sp,t1), E1=padd(sm,t2), E2=psub(sm,t2), E3=psub(sp,t1);
    ull O0=pfma(pk1(C1),v[1], pfma(pk1( C3),v[3], pfma(pk1( C5),v[5], pmul(pk1( C7),v[7]))));
    ull O1=pfma(pk1(C3),v[1], pfma(pk1(-C7),v[3], pfma(pk1(-C1),v[5], pmul(pk1(-C5),v[7]))));
    ull O2=pfma(pk1(C5),v[1], pfma(pk1(-C1),v[3], pfma(pk1( C7),v[5], pmul(pk1( C3),v[7]))));
    ull O3=pfma(pk1(C7),v[1], pfma(pk1(-C5),v[3], pfma(pk1( C3),v[5], pmul(pk1(-C1),v[7]))));
    v[0]=padd(E0,O0); v[7]=psub(E0,O0);
    v[1]=padd(E1,O1); v[6]=psub(E1,O1);
    v[2]=padd(E2,O2); v[5]=psub(E2,O2);
    v[3]=padd(E3,O3); v[4]=psub(E3,O3);
}

// ---- quant/dequant of one packed coefficient pair ----
__device__ __forceinline__ ull quant_pair(ull sv, float q, float rq, float nq)
{
    float2 s = unpk(sv);
    float d0 = s.x * rq,  d1 = s.y * rq;
    float r0 = rintf(d0), r1 = rintf(d1);
    float e0 = fmaf(r0, nq, s.x) * rq;
    float e1 = fmaf(r1, nq, s.y) * rq;
    float o0 = fmaf(e0 * e0, e0, r0) * q;
    float o1 = fmaf(e1 * e1, e1, r1) * q;
    return pk(o0, o1);
}

// Bank-conflict-free layout: group pitch 84 ull, row pitch 10 ull.
#define GP 84
#define RP 10
#define WBUF (4 * GP)   // per-warp buffer size in ull

// ---- merged transpose of Y,U (two buffers) then V (buffer 0) ----
__device__ __forceinline__ void xposeYUV(ull Y[8], ull U[8], ull V[8],
                                         ull* b0, ull* b1, int r)
{
    ull* w0 = b0 + RP * r;
    ull* w1 = b1 + RP * r;
    #pragma unroll
    for (int k = 0; k < 8; k += 2) {
        *reinterpret_cast<ulonglong2*>(w0 + k) = make_ulonglong2(Y[k], Y[k+1]);
        *reinterpret_cast<ulonglong2*>(w1 + k) = make_ulonglong2(U[k], U[k+1]);
    }
    __syncwarp();
    #pragma unroll
    for (int k = 0; k < 8; ++k) {
        Y[k] = b0[RP * k + r];
        U[k] = b1[RP * k + r];
    }
    __syncwarp();
    #pragma unroll
    for (int k = 0; k < 8; k += 2)
        *reinterpret_cast<ulonglong2*>(w0 + k) = make_ulonglong2(V[k], V[k+1]);
    __syncwarp();
    #pragma unroll
    for (int k = 0; k < 8; ++k) V[k] = b0[RP * k + r];
    __syncwarp();
}

__global__ __launch_bounds__(256, 2)
void jpeg_roundtrip_kernel(const float* __restrict__ in, float* __restrict__ out)
{
    // two per-warp transpose buffers: 2 x 8 warps x 336 ull = 43008 B
    __shared__ __align__(16) ull xb[2 * 8 * WBUF];
    // interleaved (q, rq) tables: [ch][i][r][2]
    __shared__ float qt[256];

    const int tid  = threadIdx.x;
    const int warp = tid >> 5;
    const int lane = tid & 31;
    const int r    = lane >> 2;
    const int g    = lane & 3;

    {   // build interleaved quant table
        int w  = tid & 1, rr = (tid >> 1) & 7, ii = (tid >> 4) & 7, ch = tid >> 7;
        int si = ch * 64 + ii * 8 + rr;
        qt[tid] = w ? cRQf[si] : cQf[si];
    }

    ull* b0 = xb + warp * WBUF + g * GP;
    ull* b1 = xb + (8 + warp) * WBUF + g * GP;

    const int p    = warp * 4 + g;
    const int x0   = blockIdx.x * 512 + p * 16;
    const int y    = blockIdx.y * 8 + r;
    const int base = y * IMG_W + x0;

    // ---- load RGB (two blocks) ----
    float4 R0a = *(const float4*)(in + base);
    float4 R0b = *(const float4*)(in + base + 4);
    float4 R1a = *(const float4*)(in + base + 8);
    float4 R1b = *(const float4*)(in + base + 12);
    float4 G0a = *(const float4*)(in + base + PLANE);
    float4 G0b = *(const float4*)(in + base + PLANE + 4);
    float4 G1a = *(const float4*)(in + base + PLANE + 8);
    float4 G1b = *(const float4*)(in + base + PLANE + 12);
    float4 B0a = *(const float4*)(in + base + 2*PLANE);
    float4 B0b = *(const float4*)(in + base + 2*PLANE + 4);
    float4 B1a = *(const float4*)(in + base + 2*PLANE + 8);
    float4 B1b = *(const float4*)(in + base + 2*PLANE + 12);

    __syncthreads();   // quant table ready

    float Rc0[8] = {R0a.x,R0a.y,R0a.z,R0a.w, R0b.x,R0b.y,R0b.z,R0b.w};
    float Rc1[8] = {R1a.x,R1a.y,R1a.z,R1a.w, R1b.x,R1b.y,R1b.z,R1b.w};
    float Gc0[8] = {G0a.x,G0a.y,G0a.z,G0a.w, G0b.x,G0b.y,G0b.z,G0b.w};
    float Gc1[8] = {G1a.x,G1a.y,G1a.z,G1a.w, G1b.x,G1b.y,G1b.z,G1b.w};
    float Bc0[8] = {B0a.x,B0a.y,B0a.z,B0a.w, B0b.x,B0b.y,B0b.z,B0b.w};
    float Bc1[8] = {B1a.x,B1a.y,B1a.z,B1a.w, B1b.x,B1b.y,B1b.z,B1b.w};

    // ---- forward color, packed {block0, block1} ----
    ull Yp[8], Up[8], Vp[8];
    #pragma unroll
    for (int k = 0; k < 8; ++k) {
        ull Rp = pk(Rc0[k], Rc1[k]);
        ull Gp = pk(Gc0[k], Gc1[k]);
        ull Bp = pk(Bc0[k], Bc1[k]);
        Yp[k] = pfma(Bp, pk1(0.114f), pfma(Gp, pk1(0.587f), pmul(Rp, pk1(0.299f))));
        Up[k] = pfma(Rp, pk1(-0.168736f), pfma(Gp, pk1(-0.331264f), pfma(Bp, pk1(0.5f), pk1(128.0f))));
        Vp[k] = pfma(Rp, pk1(0.5f), pfma(Gp, pk1(-0.418688f), pfma(Bp, pk1(-0.081312f), pk1(128.0f))));
    }

    // ---- stage 1: column DCT, all channels interleaved ----
    fdct8p(Yp); fdct8p(Up); fdct8p(Vp);
    xposeYUV(Yp, Up, Vp, b0, b1, r);

    // ---- stage 2: row DCT, interleaved ----
    fdct8p(Yp); fdct8p(Up); fdct8p(Vp);

    // ---- quant/dequant (U,V share chroma constants) ----
    #pragma unroll
    for (int i = 0; i < 8; ++i) {
        float2 qy = *(const float2*)(qt + i * 16 + r * 2);
        float2 qc = *(const float2*)(qt + 128 + i * 16 + r * 2);
        Yp[i] = quant_pair(Yp[i], qy.x, qy.y, -qy.x);
        Up[i] = quant_pair(Up[i], qc.x, qc.y, -qc.x);
        Vp[i] = quant_pair(Vp[i], qc.x, qc.y, -qc.x);
    }

    // ---- stage 3: column IDCT, interleaved ----
    idct8p(Yp); idct8p(Up); idct8p(Vp);
    xposeYUV(Yp, Up, Vp, b0, b1, r);

    // ---- stage 4: row IDCT, interleaved ----
    idct8p(Yp); idct8p(Up); idct8p(Vp);

    // ---- folded inverse color + normalize, packed ----
    float Ro[8], R1o[8], Go[8], G1o[8], Bo[8], B1o[8];
    #pragma unroll
    for (int k = 0; k < 8; ++k) {
        ull Rp = pfma(Yp[k], pk1(NC_A0), pfma(Up[k], pk1(NC_B0), pfma(Vp[k], pk1(NC_C0), pk1(NC_K0))));
        ull Gp = pfma(Yp[k], pk1(NC_A1), pfma(Up[k], pk1(NC_B1), pfma(Vp[k], pk1(NC_C1), pk1(NC_K1))));
        ull Bp = pfma(Yp[k], pk1(NC_A2), pfma(Up[k], pk1(NC_B2), pfma(Vp[k], pk1(NC_C2), pk1(NC_K2))));
        float2 rv = unpk(Rp), gv = unpk(Gp), bv = unpk(Bp);
        Ro[k] = rv.x; R1o[k] = rv.y;
        Go[k] = gv.x; G1o[k] = gv.y;
        Bo[k] = bv.x; B1o[k] = bv.y;
    }
    *(float4*)(out + base)                 = make_float4(Ro[0],Ro[1],Ro[2],Ro[3]);
    *(float4*)(out + base + 4)             = make_float4(Ro[4],Ro[5],Ro[6],Ro[7]);
    *(float4*)(out + base + 8)             = make_float4(R1o[0],R1o[1],R1o[2],R1o[3]);
    *(float4*)(out + base + 12)            = make_float4(R1o[4],R1o[5],R1o[6],R1o[7]);
    *(float4*)(out + base + PLANE)         = make_float4(Go[0],Go[1],Go[2],Go[3]);
    *(float4*)(out + base + PLANE + 4)     = make_float4(Go[4],Go[5],Go[6],Go[7]);
    *(float4*)(out + base + PLANE + 8)     = make_float4(G1o[0],G1o[1],G1o[2],G1o[3]);
    *(float4*)(out + base + PLANE + 12)    = make_float4(G1o[4],G1o[5],G1o[6],G1o[7]);
    *(float4*)(out + base + 2*PLANE)       = make_float4(Bo[0],Bo[1],Bo[2],Bo[3]);
    *(float4*)(out + base + 2*PLANE + 4)   = make_float4(Bo[4],Bo[5],Bo[6],Bo[7]);
    *(float4*)(out + base + 2*PLANE + 8)   = make_float4(B1o[0],B1o[1],B1o[2],B1o[3]);
    *(float4*)(out + base + 2*PLANE + 12)  = make_float4(B1o[4],B1o[5],B1o[6],B1o[7]);
}

extern "C" void kernel_launch(void* const* d_in, const int* in_sizes, int n_in,
                              void* d_out, int out_size)
{
    const float* in = (const float*)d_in[0];
    float* out = (float*)d_out;
    dim3 grid(IMG_W / 512, IMG_H / 8);
    jpeg_roundtrip_kernel<<<grid, 256>>>(in, out);
}

// round 7
// speedup vs baseline: 1.0686x; 1.0675x over previous
#include <cuda_runtime.h>
#include <cstring>

// Fused JPEG round-trip. Thread owns TWO horizontally adjacent 8x8 blocks,
// all three channels packed f32x2 {block0,block1}. Y/U/V pipelines interleaved;
// transposes via per-warp bank-conflict-free smem. launch_bounds(256,3) to fit
// 85 regs -> 3 CTAs/SM (the 86-reg version was 1 register over the boundary).
// Input : d_in[0] = float32 [1,3,2048,2048]; Output: float32 [1,3*2048*2048]

#define IMG_W  2048
#define IMG_H  2048
#define PLANE  (IMG_W * IMG_H)

// DCT basis constants (fp32 round of the reference matrix entries)
#define C1 0.4903926402f
#define C2 0.4619397663f
#define C3 0.4157348062f
#define C4 0.3535533906f
#define C5 0.2777851165f
#define C6 0.1913417162f
#define C7 0.0975451610f

// Quant tables, luma then chroma (Q=50 -> s=1)
__constant__ float cQf[128] = {
    16,11,10,16,24,40,51,61,  12,12,14,19,26,58,60,55,
    14,13,16,24,40,57,69,56,  14,17,22,29,51,87,80,62,
    18,22,37,56,68,109,103,77, 24,35,55,64,81,104,113,92,
    49,64,78,87,103,121,120,101, 72,92,95,98,112,100,103,99,
    17,18,24,47,99,99,99,99,  18,21,26,66,99,99,99,99,
    24,26,56,99,99,99,99,99,  47,66,99,99,99,99,99,99,
    99,99,99,99,99,99,99,99,  99,99,99,99,99,99,99,99,
    99,99,99,99,99,99,99,99,  99,99,99,99,99,99,99,99 };
__constant__ float cRQf[128] = {
    1.f/16,1.f/11,1.f/10,1.f/16,1.f/24,1.f/40,1.f/51,1.f/61,
    1.f/12,1.f/12,1.f/14,1.f/19,1.f/26,1.f/58,1.f/60,1.f/55,
    1.f/14,1.f/13,1.f/16,1.f/24,1.f/40,1.f/57,1.f/69,1.f/56,
    1.f/14,1.f/17,1.f/22,1.f/29,1.f/51,1.f/87,1.f/80,1.f/62,
    1.f/18,1.f/22,1.f/37,1.f/56,1.f/68,1.f/109,1.f/103,1.f/77,
    1.f/24,1.f/35,1.f/55,1.f/64,1.f/81,1.f/104,1.f/113,1.f/92,
    1.f/49,1.f/64,1.f/78,1.f/87,1.f/103,1.f/121,1.f/120,1.f/101,
    1.f/72,1.f/92,1.f/95,1.f/98,1.f/112,1.f/100,1.f/103,1.f/99,
    1.f/17,1.f/18,1.f/24,1.f/47,1.f/99,1.f/99,1.f/99,1.f/99,
    1.f/18,1.f/21,1.f/26,1.f/66,1.f/99,1.f/99,1.f/99,1.f/99,
    1.f/24,1.f/26,1.f/56,1.f/99,1.f/99,1.f/99,1.f/99,1.f/99,
    1.f/47,1.f/66,1.f/99,1.f/99,1.f/99,1.f/99,1.f/99,1.f/99,
    1.f/99,1.f/99,1.f/99,1.f/99,1.f/99,1.f/99,1.f/99,1.f/99,
    1.f/99,1.f/99,1.f/99,1.f/99,1.f/99,1.f/99,1.f/99,1.f/99,
    1.f/99,1.f/99,1.f/99,1.f/99,1.f/99,1.f/99,1.f/99,1.f/99,
    1.f/99,1.f/99,1.f/99,1.f/99,1.f/99,1.f/99,1.f/99,1.f/99 };

// Folded inverse-color + normalization: out_c = NC_Ac*y + NC_Bc*u + NC_Cc*v + NC_Kc
#define NC_A0 0.0158730159f
#define NC_B0 (-1.93476190e-8f)
#define NC_C0 0.0222539619f
#define NC_K0 (-4.8373935f)
#define NC_A1 0.0161030596f
#define NC_B1 (-0.0055416377f)
#define NC_C1 (-0.0114997768f)
#define NC_K1 0.2006247f
#define NC_A2 0.0149925037f
#define NC_B2 0.0265667181f
#define NC_C2 6.09145427e-9f
#define NC_K2 (-5.1081869f)

typedef unsigned long long ull;

// ---- packed f32x2 helpers ----
__device__ __forceinline__ ull pk(float lo, float hi) {
    float2 t = make_float2(lo, hi); ull r; memcpy(&r, &t, 8); return r;
}
__device__ __forceinline__ ull pk1(float x) { return pk(x, x); }
__device__ __forceinline__ float2 unpk(ull a) {
    float2 t; memcpy(&t, &a, 8); return t;
}
__device__ __forceinline__ ull padd(ull a, ull b) {
    ull r; asm("add.rn.f32x2 %0,%1,%2;" : "=l"(r) : "l"(a), "l"(b)); return r;
}
__device__ __forceinline__ ull pmul(ull a, ull b) {
    ull r; asm("mul.rn.f32x2 %0,%1,%2;" : "=l"(r) : "l"(a), "l"(b)); return r;
}
__device__ __forceinline__ ull pfma(ull a, ull b, ull c) {
    ull r; asm("fma.rn.f32x2 %0,%1,%2,%3;" : "=l"(r) : "l"(a), "l"(b), "l"(c)); return r;
}
__device__ __forceinline__ ull psub(ull a, ull b) { return pfma(b, pk1(-1.0f), a); } // exact a-b

// ---- packed 8-pt transforms ----
__device__ __forceinline__ void fdct8p(ull v[8]) {
    ull e0=padd(v[0],v[7]), e1=padd(v[1],v[6]), e2=padd(v[2],v[5]), e3=padd(v[3],v[4]);
    ull o0=psub(v[0],v[7]), o1=psub(v[1],v[6]), o2=psub(v[2],v[5]), o3=psub(v[3],v[4]);
    ull s03=padd(e0,e3), s12=padd(e1,e2), d03=psub(e0,e3), d12=psub(e1,e2);
    v[0]=pmul(pk1(C4), padd(s03,s12));
    v[4]=pmul(pk1(C4), psub(s03,s12));
    v[2]=pfma(pk1(C2),d03, pmul(pk1( C6),d12));
    v[6]=pfma(pk1(C6),d03, pmul(pk1(-C2),d12));
    v[1]=pfma(pk1(C1),o0, pfma(pk1( C3),o1, pfma(pk1( C5),o2, pmul(pk1( C7),o3))));
    v[3]=pfma(pk1(C3),o0, pfma(pk1(-C7),o1, pfma(pk1(-C1),o2, pmul(pk1(-C5),o3))));
    v[5]=pfma(pk1(C5),o0, pfma(pk1(-C1),o1, pfma(pk1( C7),o2, pmul(pk1( C3),o3))));
    v[7]=pfma(pk1(C7),o0, pfma(pk1(-C5),o1, pfma(pk1( C3),o2, pmul(pk1(-C1),o3))));
}
__device__ __forceinline__ void idct8p(ull v[8]) {
    ull sp=pmul(pk1(C4), padd(v[0],v[4]));
    ull sm=pmul(pk1(C4), psub(v[0],v[4]));
    ull t1=pfma(pk1(C2),v[2], pmul(pk1( C6),v[6]));
    ull t2=pfma(pk1(C6),v[2], pmul(pk1(-C2),v[6]));
    ull E0=padd(sp,t1), E1=padd(sm,t2), E2=psub(sm,t2), E3=psub(sp,t1);
    ull O0=pfma(pk1(C1),v[1], pfma(pk1( C3),v[3], pfma(pk1( C5),v[5], pmul(pk1( C7),v[7]))));
    ull O1=pfma(pk1(C3),v[1], pfma(pk1(-C7),v[3], pfma(pk1(-C1),v[5], pmul(pk1(-C5),v[7]))));
    ull O2=pfma(pk1(C5),v[1], pfma(pk1(-C1),v[3], pfma(pk1( C7),v[5], pmul(pk1( C3),v[7]))));
    ull O3=pfma(pk1(C7),v[1], pfma(pk1(-C5),v[3], pfma(pk1( C3),v[5], pmul(pk1(-C1),v[7]))));
    v[0]=padd(E0,O0); v[7]=psub(E0,O0);
    v[1]=padd(E1,O1); v[6]=psub(E1,O1);
    v[2]=padd(E2,O2); v[5]=psub(E2,O2);
    v[3]=padd(E3,O3); v[4]=psub(E3,O3);
}

// ---- quant/dequant of one packed coefficient pair ----
__device__ __forceinline__ ull quant_pair(ull sv, float q, float rq, float nq)
{
    float2 s = unpk(sv);
    float d0 = s.x * rq,  d1 = s.y * rq;
    float r0 = rintf(d0), r1 = rintf(d1);
    float e0 = fmaf(r0, nq, s.x) * rq;
    float e1 = fmaf(r1, nq, s.y) * rq;
    float o0 = fmaf(e0 * e0, e0, r0) * q;
    float o1 = fmaf(e1 * e1, e1, r1) * q;
    return pk(o0, o1);
}

// Bank-conflict-free layout: group pitch 84 ull, row pitch 10 ull.
#define GP 84
#define RP 10
#define WBUF (4 * GP)   // per-warp buffer size in ull

// ---- merged transpose of Y,U (two buffers) then V (buffer 0) ----
__device__ __forceinline__ void xposeYUV(ull Y[8], ull U[8], ull V[8],
                                         ull* b0, ull* b1, int r)
{
    ull* w0 = b0 + RP * r;
    ull* w1 = b1 + RP * r;
    #pragma unroll
    for (int k = 0; k < 8; k += 2) {
        *reinterpret_cast<ulonglong2*>(w0 + k) = make_ulonglong2(Y[k], Y[k+1]);
        *reinterpret_cast<ulonglong2*>(w1 + k) = make_ulonglong2(U[k], U[k+1]);
    }
    __syncwarp();
    #pragma unroll
    for (int k = 0; k < 8; ++k) {
        Y[k] = b0[RP * k + r];
        U[k] = b1[RP * k + r];
    }
    __syncwarp();
    #pragma unroll
    for (int k = 0; k < 8; k += 2)
        *reinterpret_cast<ulonglong2*>(w0 + k) = make_ulonglong2(V[k], V[k+1]);
    __syncwarp();
    #pragma unroll
    for (int k = 0; k < 8; ++k) V[k] = b0[RP * k + r];
    __syncwarp();
}

__global__ __launch_bounds__(256, 3)
void jpeg_roundtrip_kernel(const float* __restrict__ in, float* __restrict__ out)
{
    // two per-warp transpose buffers: 2 x 8 warps x 336 ull = 43008 B
    __shared__ __align__(16) ull xb[2 * 8 * WBUF];
    // interleaved (q, rq) tables: [ch][i][r][2]
    __shared__ float qt[256];

    const int tid  = threadIdx.x;
    const int warp = tid >> 5;
    const int lane = tid & 31;
    const int r    = lane >> 2;
    const int g    = lane & 3;

    {   // build interleaved quant table
        int w  = tid & 1, rr = (tid >> 1) & 7, ii = (tid >> 4) & 7, ch = tid >> 7;
        int si = ch * 64 + ii * 8 + rr;
        qt[tid] = w ? cRQf[si] : cQf[si];
    }

    ull* b0 = xb + warp * WBUF + g * GP;
    ull* b1 = xb + (8 + warp) * WBUF + g * GP;

    const int p    = warp * 4 + g;
    const int x0   = blockIdx.x * 512 + p * 16;
    const int y    = blockIdx.y * 8 + r;
    const int base = y * IMG_W + x0;

    // ---- load RGB (two blocks) ----
    float4 R0a = *(const float4*)(in + base);
    float4 R0b = *(const float4*)(in + base + 4);
    float4 R1a = *(const float4*)(in + base + 8);
    float4 R1b = *(const float4*)(in + base + 12);
    float4 G0a = *(const float4*)(in + base + PLANE);
    float4 G0b = *(const float4*)(in + base + PLANE + 4);
    float4 G1a = *(const float4*)(in + base + PLANE + 8);
    float4 G1b = *(const float4*)(in + base + PLANE + 12);
    float4 B0a = *(const float4*)(in + base + 2*PLANE);
    float4 B0b = *(const float4*)(in + base + 2*PLANE + 4);
    float4 B1a = *(const float4*)(in + base + 2*PLANE + 8);
    float4 B1b = *(const float4*)(in + base + 2*PLANE + 12);

    __syncthreads();   // quant table ready

    float Rc0[8] = {R0a.x,R0a.y,R0a.z,R0a.w, R0b.x,R0b.y,R0b.z,R0b.w};
    float Rc1[8] = {R1a.x,R1a.y,R1a.z,R1a.w, R1b.x,R1b.y,R1b.z,R1b.w};
    float Gc0[8] = {G0a.x,G0a.y,G0a.z,G0a.w, G0b.x,G0b.y,G0b.z,G0b.w};
    float Gc1[8] = {G1a.x,G1a.y,G1a.z,G1a.w, G1b.x,G1b.y,G1b.z,G1b.w};
    float Bc0[8] = {B0a.x,B0a.y,B0a.z,B0a.w, B0b.x,B0b.y,B0b.z,B0b.w};
    float Bc1[8] = {B1a.x,B1a.y,B1a.z,B1a.w, B1b.x,B1b.y,B1b.z,B1b.w};

    // ---- forward color, packed {block0, block1} ----
    ull Yp[8], Up[8], Vp[8];
    #pragma unroll
    for (int k = 0; k < 8; ++k) {
        ull Rp = pk(Rc0[k], Rc1[k]);
        ull Gp = pk(Gc0[k], Gc1[k]);
        ull Bp = pk(Bc0[k], Bc1[k]);
        Yp[k] = pfma(Bp, pk1(0.114f), pfma(Gp, pk1(0.587f), pmul(Rp, pk1(0.299f))));
        Up[k] = pfma(Rp, pk1(-0.168736f), pfma(Gp, pk1(-0.331264f), pfma(Bp, pk1(0.5f), pk1(128.0f))));
        Vp[k] = pfma(Rp, pk1(0.5f), pfma(Gp, pk1(-0.418688f), pfma(Bp, pk1(-0.081312f), pk1(128.0f))));
    }

    // ---- stage 1: column DCT, all channels interleaved ----
    fdct8p(Yp); fdct8p(Up); fdct8p(Vp);
    xposeYUV(Yp, Up, Vp, b0, b1, r);

    // ---- stage 2: row DCT, interleaved ----
    fdct8p(Yp); fdct8p(Up); fdct8p(Vp);

    // ---- quant/dequant (U,V share chroma constants) ----
    #pragma unroll
    for (int i = 0; i < 8; ++i) {
        float2 qy = *(const float2*)(qt + i * 16 + r * 2);
        float2 qc = *(const float2*)(qt + 128 + i * 16 + r * 2);
        Yp[i] = quant_pair(Yp[i], qy.x, qy.y, -qy.x);
        Up[i] = quant_pair(Up[i], qc.x, qc.y, -qc.x);
        Vp[i] = quant_pair(Vp[i], qc.x, qc.y, -qc.x);
    }

    // ---- stage 3: column IDCT, interleaved ----
    idct8p(Yp); idct8p(Up); idct8p(Vp);
    xposeYUV(Yp, Up, Vp, b0, b1, r);

    // ---- stage 4: row IDCT, interleaved ----
    idct8p(Yp); idct8p(Up); idct8p(Vp);

    // ---- folded inverse color + normalize, packed ----
    float Ro[8], R1o[8], Go[8], G1o[8], Bo[8], B1o[8];
    #pragma unroll
    for (int k = 0; k < 8; ++k) {
        ull Rp = pfma(Yp[k], pk1(NC_A0), pfma(Up[k], pk1(NC_B0), pfma(Vp[k], pk1(NC_C0), pk1(NC_K0))));
        ull Gp = pfma(Yp[k], pk1(NC_A1), pfma(Up[k], pk1(NC_B1), pfma(Vp[k], pk1(NC_C1), pk1(NC_K1))));
        ull Bp = pfma(Yp[k], pk1(NC_A2), pfma(Up[k], pk1(NC_B2), pfma(Vp[k], pk1(NC_C2), pk1(NC_K2))));
        float2 rv = unpk(Rp), gv = unpk(Gp), bv = unpk(Bp);
        Ro[k] = rv.x; R1o[k] = rv.y;
        Go[k] = gv.x; G1o[k] = gv.y;
        Bo[k] = bv.x; B1o[k] = bv.y;
    }
    *(float4*)(out + base)                 = make_float4(Ro[0],Ro[1],Ro[2],Ro[3]);
    *(float4*)(out + base + 4)             = make_float4(Ro[4],Ro[5],Ro[6],Ro[7]);
    *(float4*)(out + base + 8)             = make_float4(R1o[0],R1o[1],R1o[2],R1o[3]);
    *(float4*)(out + base + 12)            = make_float4(R1o[4],R1o[5],R1o[6],R1o[7]);
    *(float4*)(out + base + PLANE)         = make_float4(Go[0],Go[1],Go[2],Go[3]);
    *(float4*)(out + base + PLANE + 4)     = make_float4(Go[4],Go[5],Go[6],Go[7]);
    *(float4*)(out + base + PLANE + 8)     = make_float4(G1o[0],G1o[1],G1o[2],G1o[3]);
    *(float4*)(out + base + PLANE + 12)    = make_float4(G1o[4],G1o[5],G1o[6],G1o[7]);
    *(float4*)(out + base + 2*PLANE)       = make_float4(Bo[0],Bo[1],Bo[2],Bo[3]);
    *(float4*)(out + base + 2*PLANE + 4)   = make_float4(Bo[4],Bo[5],Bo[6],Bo[7]);
    *(float4*)(out + base + 2*PLANE + 8)   = make_float4(B1o[0],B1o[1],B1o[2],B1o[3]);
    *(float4*)(out + base + 2*PLANE + 12)  = make_float4(B1o[4],B1o[5],B1o[6],B1o[7]);
}

extern "C" void kernel_launch(void* const* d_in, const int* in_sizes, int n_in,
                              void* d_out, int out_size)
{
    const float* in = (const float*)d_in[0];
    float* out = (float*)d_out;
    dim3 grid(IMG_W / 512, IMG_H / 8);
    jpeg_roundtrip_kernel<<<grid, 256>>>(in, out);
}

// round 8
// speedup vs baseline: 1.3658x; 1.2782x over previous
#include <cuda_runtime.h>
#include <cstring>

// Fused JPEG round-trip. Thread owns row r of ONE 8x8 block: Y scalar (8 regs),
// U+V packed f32x2 (16 regs). Transposes via per-warp conflict-free smem.
// launch_bounds(256,4) -> ~64 regs -> 4 CTAs/SM.
// Input : d_in[0] = float32 [1,3,2048,2048]; Output: float32 [1,3*2048*2048]

#define IMG_W  2048
#define IMG_H  2048
#define PLANE  (IMG_W * IMG_H)

#define C1 0.4903926402f
#define C2 0.4619397663f
#define C3 0.4157348062f
#define C4 0.3535533906f
#define C5 0.2777851165f
#define C6 0.1913417162f
#define C7 0.0975451610f

__constant__ float cQf[128] = {
    16,11,10,16,24,40,51,61,  12,12,14,19,26,58,60,55,
    14,13,16,24,40,57,69,56,  14,17,22,29,51,87,80,62,
    18,22,37,56,68,109,103,77, 24,35,55,64,81,104,113,92,
    49,64,78,87,103,121,120,101, 72,92,95,98,112,100,103,99,
    17,18,24,47,99,99,99,99,  18,21,26,66,99,99,99,99,
    24,26,56,99,99,99,99,99,  47,66,99,99,99,99,99,99,
    99,99,99,99,99,99,99,99,  99,99,99,99,99,99,99,99,
    99,99,99,99,99,99,99,99,  99,99,99,99,99,99,99,99 };
__constant__ float cRQf[128] = {
    1.f/16,1.f/11,1.f/10,1.f/16,1.f/24,1.f/40,1.f/51,1.f/61,
    1.f/12,1.f/12,1.f/14,1.f/19,1.f/26,1.f/58,1.f/60,1.f/55,
    1.f/14,1.f/13,1.f/16,1.f/24,1.f/40,1.f/57,1.f/69,1.f/56,
    1.f/14,1.f/17,1.f/22,1.f/29,1.f/51,1.f/87,1.f/80,1.f/62,
    1.f/18,1.f/22,1.f/37,1.f/56,1.f/68,1.f/109,1.f/103,1.f/77,
    1.f/24,1.f/35,1.f/55,1.f/64,1.f/81,1.f/104,1.f/113,1.f/92,
    1.f/49,1.f/64,1.f/78,1.f/87,1.f/103,1.f/121,1.f/120,1.f/101,
    1.f/72,1.f/92,1.f/95,1.f/98,1.f/112,1.f/100,1.f/103,1.f/99,
    1.f/17,1.f/18,1.f/24,1.f/47,1.f/99,1.f/99,1.f/99,1.f/99,
    1.f/18,1.f/21,1.f/26,1.f/66,1.f/99,1.f/99,1.f/99,1.f/99,
    1.f/24,1.f/26,1.f/56,1.f/99,1.f/99,1.f/99,1.f/99,1.f/99,
    1.f/47,1.f/66,1.f/99,1.f/99,1.f/99,1.f/99,1.f/99,1.f/99,
    1.f/99,1.f/99,1.f/99,1.f/99,1.f/99,1.f/99,1.f/99,1.f/99,
    1.f/99,1.f/99,1.f/99,1.f/99,1.f/99,1.f/99,1.f/99,1.f/99,
    1.f/99,1.f/99,1.f/99,1.f/99,1.f/99,1.f/99,1.f/99,1.f/99,
    1.f/99,1.f/99,1.f/99,1.f/99,1.f/99,1.f/99,1.f/99,1.f/99 };

// inv(W)
#define IW01 (-1.2189e-6f)
#define IW02  1.4019996f
#define IW11 (-0.34413570f)
#define IW12 (-0.71413614f)
#define IW21  1.7720001f
#define IW22  4.0630e-7f
#define MEAN0 0.49137255f
#define MEAN1 0.48235294f
#define MEAN2 0.44666666f
#define ISTD0 4.04761905f
#define ISTD1 4.10628019f
#define ISTD2 3.82308846f

typedef unsigned long long ull;

// ---- packed f32x2 helpers ----
__device__ __forceinline__ ull pk(float lo, float hi) {
    float2 t = make_float2(lo, hi); ull r; memcpy(&r, &t, 8); return r;
}
__device__ __forceinline__ ull pk1(float x) { return pk(x, x); }
__device__ __forceinline__ float2 unpk(ull a) {
    float2 t; memcpy(&t, &a, 8); return t;
}
__device__ __forceinline__ ull padd(ull a, ull b) {
    ull r; asm("add.rn.f32x2 %0,%1,%2;" : "=l"(r) : "l"(a), "l"(b)); return r;
}
__device__ __forceinline__ ull pmul(ull a, ull b) {
    ull r; asm("mul.rn.f32x2 %0,%1,%2;" : "=l"(r) : "l"(a), "l"(b)); return r;
}
__device__ __forceinline__ ull pfma(ull a, ull b, ull c) {
    ull r; asm("fma.rn.f32x2 %0,%1,%2,%3;" : "=l"(r) : "l"(a), "l"(b), "l"(c)); return r;
}
__device__ __forceinline__ ull psub(ull a, ull b) { return pfma(b, pk1(-1.0f), a); }

// ---- scalar 8-pt transforms ----
__device__ __forceinline__ void fdct8(float v[8]) {
    float e0=v[0]+v[7], e1=v[1]+v[6], e2=v[2]+v[5], e3=v[3]+v[4];
    float o0=v[0]-v[7], o1=v[1]-v[6], o2=v[2]-v[5], o3=v[3]-v[4];
    float s03=e0+e3, s12=e1+e2, d03=e0-e3, d12=e1-e2;
    v[0]=C4*(s03+s12);
    v[4]=C4*(s03-s12);
    v[2]=fmaf(C2,d03, C6*d12);
    v[6]=fmaf(C6,d03,-C2*d12);
    v[1]=fmaf(C1,o0,fmaf( C3,o1,fmaf( C5,o2, C7*o3)));
    v[3]=fmaf(C3,o0,fmaf(-C7,o1,fmaf(-C1,o2,-C5*o3)));
    v[5]=fmaf(C5,o0,fmaf(-C1,o1,fmaf( C7,o2, C3*o3)));
    v[7]=fmaf(C7,o0,fmaf(-C5,o1,fmaf( C3,o2,-C1*o3)));
}
__device__ __forceinline__ void idct8(float v[8]) {
    float sp=C4*(v[0]+v[4]), sm=C4*(v[0]-v[4]);
    float t1=fmaf(C2,v[2], C6*v[6]);
    float t2=fmaf(C6,v[2],-C2*v[6]);
    float E0=sp+t1, E1=sm+t2, E2=sm-t2, E3=sp-t1;
    float O0=fmaf(C1,v[1],fmaf( C3,v[3],fmaf( C5,v[5], C7*v[7])));
    float O1=fmaf(C3,v[1],fmaf(-C7,v[3],fmaf(-C1,v[5],-C5*v[7])));
    float O2=fmaf(C5,v[1],fmaf(-C1,v[3],fmaf( C7,v[5], C3*v[7])));
    float O3=fmaf(C7,v[1],fmaf(-C5,v[3],fmaf( C3,v[5],-C1*v[7])));
    v[0]=E0+O0; v[7]=E0-O0;
    v[1]=E1+O1; v[6]=E1-O1;
    v[2]=E2+O2; v[5]=E2-O2;
    v[3]=E3+O3; v[4]=E3-O3;
}

// ---- packed 8-pt transforms ----
__device__ __forceinline__ void fdct8p(ull v[8]) {
    ull e0=padd(v[0],v[7]), e1=padd(v[1],v[6]), e2=padd(v[2],v[5]), e3=padd(v[3],v[4]);
    ull o0=psub(v[0],v[7]), o1=psub(v[1],v[6]), o2=psub(v[2],v[5]), o3=psub(v[3],v[4]);
    ull s03=padd(e0,e3), s12=padd(e1,e2), d03=psub(e0,e3), d12=psub(e1,e2);
    v[0]=pmul(pk1(C4), padd(s03,s12));
    v[4]=pmul(pk1(C4), psub(s03,s12));
    v[2]=pfma(pk1(C2),d03, pmul(pk1( C6),d12));
    v[6]=pfma(pk1(C6),d03, pmul(pk1(-C2),d12));
    v[1]=pfma(pk1(C1),o0, pfma(pk1( C3),o1, pfma(pk1( C5),o2, pmul(pk1( C7),o3))));
    v[3]=pfma(pk1(C3),o0, pfma(pk1(-C7),o1, pfma(pk1(-C1),o2, pmul(pk1(-C5),o3))));
    v[5]=pfma(pk1(C5),o0, pfma(pk1(-C1),o1, pfma(pk1( C7),o2, pmul(pk1( C3),o3))));
    v[7]=pfma(pk1(C7),o0, pfma(pk1(-C5),o1, pfma(pk1( C3),o2, pmul(pk1(-C1),o3))));
}
__device__ __forceinline__ void idct8p(ull v[8]) {
    ull sp=pmul(pk1(C4), padd(v[0],v[4]));
    ull sm=pmul(pk1(C4), psub(v[0],v[4]));
    ull t1=pfma(pk1(C2),v[2], pmul(pk1( C6),v[6]));
    ull t2=pfma(pk1(C6),v[2], pmul(pk1(-C2),v[6]));
    ull E0=padd(sp,t1), E1=padd(sm,t2), E2=psub(sm,t2), E3=psub(sp,t1);
    ull O0=pfma(pk1(C1),v[1], pfma(pk1( C3),v[3], pfma(pk1( C5),v[5], pmul(pk1( C7),v[7]))));
    ull O1=pfma(pk1(C3),v[1], pfma(pk1(-C7),v[3], pfma(pk1(-C1),v[5], pmul(pk1(-C5),v[7]))));
    ull O2=pfma(pk1(C5),v[1], pfma(pk1(-C1),v[3], pfma(pk1( C7),v[5], pmul(pk1( C3),v[7]))));
    ull O3=pfma(pk1(C7),v[1], pfma(pk1(-C5),v[3], pfma(pk1( C3),v[5], pmul(pk1(-C1),v[7]))));
    v[0]=padd(E0,O0); v[7]=psub(E0,O0);
    v[1]=padd(E1,O1); v[6]=psub(E1,O1);
    v[2]=padd(E2,O2); v[5]=psub(E2,O2);
    v[3]=padd(E3,O3); v[4]=psub(E3,O3);
}

// smem layouts (verified conflict-free):
// Y  (float): row pitch 12 (float4-aligned), group pitch 104 (104%32==8 -> read banks 8g+r distinct)
// UV (ull)  : row pitch 10 (16B-aligned),    group pitch 84  (84%16==4  -> read bank-pairs 4g+r distinct per half-warp)
#define RPY 12
#define GPY 104
#define RPU 10
#define GPU 84

__device__ __forceinline__ void xposeYUV(float vy[8], ull uv[8],
                                         float* ybg, ull* uvbg, int r)
{
    float* yw = ybg + RPY * r;
    ull*   uw = uvbg + RPU * r;
    *(float4*)(yw)     = make_float4(vy[0], vy[1], vy[2], vy[3]);
    *(float4*)(yw + 4) = make_float4(vy[4], vy[5], vy[6], vy[7]);
    #pragma unroll
    for (int k = 0; k < 8; k += 2)
        *(ulonglong2*)(uw + k) = make_ulonglong2(uv[k], uv[k+1]);
    __syncwarp();
    #pragma unroll
    for (int k = 0; k < 8; ++k) {
        vy[k] = ybg[RPY * k + r];
        uv[k] = uvbg[RPU * k + r];
    }
    __syncwarp();
}

__global__ __launch_bounds__(256, 4)
void jpeg_roundtrip_kernel(const float* __restrict__ in, float* __restrict__ out)
{
    __shared__ __align__(16) float yb[8 * 4 * GPY];   // 13312 B
    __shared__ __align__(16) ull  uvb[8 * 4 * GPU];   // 21504 B
    __shared__ float qt[256];                         // interleaved (q, rq)

    const int tid  = threadIdx.x;
    const int warp = tid >> 5;
    const int lane = tid & 31;
    const int r    = lane >> 2;
    const int g    = lane & 3;

    {   // build interleaved quant table
        int w  = tid & 1, rr = (tid >> 1) & 7, ii = (tid >> 4) & 7, ch = tid >> 7;
        int si = ch * 64 + ii * 8 + rr;
        qt[tid] = w ? cRQf[si] : cQf[si];
    }

    float* ybg  = yb  + (warp * 4 + g) * GPY;
    ull*   uvbg = uvb + (warp * 4 + g) * GPU;

    const int x0   = blockIdx.x * 256 + (warp * 4 + g) * 8;
    const int y    = blockIdx.y * 8 + r;
    const int base = y * IMG_W + x0;

    // ---- load RGB ----
    const float4 Ra = *(const float4*)(in + base);
    const float4 Rb = *(const float4*)(in + base + 4);
    const float4 Ga = *(const float4*)(in + base + PLANE);
    const float4 Gb = *(const float4*)(in + base + PLANE + 4);
    const float4 Ba = *(const float4*)(in + base + 2*PLANE);
    const float4 Bb = *(const float4*)(in + base + 2*PLANE + 4);

    __syncthreads();   // quant table ready

    float R[8] = {Ra.x,Ra.y,Ra.z,Ra.w, Rb.x,Rb.y,Rb.z,Rb.w};
    float G[8] = {Ga.x,Ga.y,Ga.z,Ga.w, Gb.x,Gb.y,Gb.z,Gb.w};
    float B[8] = {Ba.x,Ba.y,Ba.z,Ba.w, Bb.x,Bb.y,Bb.z,Bb.w};

    // ---- forward color ----
    float vY[8];
    ull   pUV[8];
    #pragma unroll
    for (int k = 0; k < 8; ++k) {
        vY[k] = 0.299f*R[k] + 0.587f*G[k] + 0.114f*B[k];
        pUV[k] = pfma(pk1(R[k]), pk(-0.168736f, 0.5f),
                 pfma(pk1(G[k]), pk(-0.331264f, -0.418688f),
                 pfma(pk1(B[k]), pk(0.5f, -0.081312f), pk1(128.0f))));
    }

    // ---- DCT: row pass, transpose, column pass ----
    fdct8(vY); fdct8p(pUV);
    xposeYUV(vY, pUV, ybg, uvbg, r);
    fdct8(vY); fdct8p(pUV);

    // ---- quant/dequant: thread holds coeff [i][r] at index i ----
    #pragma unroll
    for (int i = 0; i < 8; ++i) {
        float2 qy = *(const float2*)(qt + i * 16 + r * 2);
        float2 qc = *(const float2*)(qt + 128 + i * 16 + r * 2);
        {   // luma (scalar)
            float sv = vY[i];
            float d  = sv * qy.y;
            float rn = rintf(d);
            float e  = fmaf(-rn, qy.x, sv) * qy.y;
            vY[i]    = fmaf(e*e, e, rn) * qy.x;
        }
        {   // chroma (packed pair, shared constants)
            float2 s = unpk(pUV[i]);
            float d0 = s.x * qc.y, d1 = s.y * qc.y;
            float r0 = rintf(d0), r1 = rintf(d1);
            float e0 = fmaf(-r0, qc.x, s.x) * qc.y;
            float e1 = fmaf(-r1, qc.x, s.y) * qc.y;
            pUV[i] = pk(fmaf(e0*e0, e0, r0) * qc.x,
                        fmaf(e1*e1, e1, r1) * qc.x);
        }
    }

    // ---- IDCT: column pass, transpose, row pass ----
    idct8(vY); idct8p(pUV);
    xposeYUV(vY, pUV, ybg, uvbg, r);
    idct8(vY); idct8p(pUV);

    // ---- inverse color + normalize + store ----
    #pragma unroll
    for (int h = 0; h < 2; ++h) {
        float4 Ro, Go, Bo;
        #pragma unroll
        for (int k = 0; k < 4; ++k) {
            int c = h*4 + k;
            float yv = vY[c];
            float2 uvv = unpk(pUV[c]);
            float u = uvv.x - 128.0f;
            float v = uvv.y - 128.0f;
            float Rv = fmaf(IW01, u, fmaf(IW02, v, yv));
            float Gv = fmaf(IW11, u, fmaf(IW12, v, yv));
            float Bv = fmaf(IW21, u, fmaf(IW22, v, yv));
            ((float*)&Ro)[k] = (Rv * (1.0f/255.0f) - MEAN0) * ISTD0;
            ((float*)&Go)[k] = (Gv * (1.0f/255.0f) - MEAN1) * ISTD1;
            ((float*)&Bo)[k] = (Bv * (1.0f/255.0f) - MEAN2) * ISTD2;
        }
        *(float4*)(out + base + h*4)           = Ro;
        *(float4*)(out + base + PLANE + h*4)   = Go;
        *(float4*)(out + base + 2*PLANE + h*4) = Bo;
    }
}

extern "C" void kernel_launch(void* const* d_in, const int* in_sizes, int n_in,
                              void* d_out, int out_size)
{
    const float* in = (const float*)d_in[0];
    float* out = (float*)d_out;
    dim3 grid(IMG_W / 256, IMG_H / 8);
    jpeg_roundtrip_kernel<<<grid, 256>>>(in, out);
}